// round 11
// baseline (speedup 1.0000x reference)
#include <cuda_runtime.h>
#include <cstdint>

#define B_  8
#define C_  512
#define N_  1024
#define NH  8
#define CH  64
#define G_  32
#define CPG 16
#define EPS 1e-5f

// ---------------- static scratch ----------------
__device__ float g_hn  [(long long)B_ * C_ * N_];
__device__ float g_qkv [(long long)B_ * 3 * C_ * N_];
__device__ float g_att [(long long)B_ * C_ * N_];
__device__ float g_proj[(long long)B_ * C_ * N_];

// ---------------- helpers ----------------
__device__ __forceinline__ uint32_t f2tf(float f) {
    uint32_t u;
    asm("cvt.rna.tf32.f32 %0, %1;" : "=r"(u) : "f"(f));
    return u;
}
__device__ __forceinline__ float ex2f(float x) {
    float y;
    asm("ex2.approx.f32 %0, %1;" : "=f"(y) : "f"(x));
    return y;
}
__device__ __forceinline__ void cp16(uint32_t dst, const void* src) {
    asm volatile("cp.async.cg.shared.global [%0], [%1], 16;" :: "r"(dst), "l"(src));
}
__device__ __forceinline__ void cp_commit() {
    asm volatile("cp.async.commit_group;" ::: "memory");
}
template<int NN>
__device__ __forceinline__ void cp_wait() {
    asm volatile("cp.async.wait_group %0;" :: "n"(NN) : "memory");
}
// k-slot remap convention: slot tig <-> mem col kk+2*tig, slot tig+4 <-> kk+2*tig+1
// (valid when BOTH A and B follow it; contraction order is irrelevant)
__device__ __forceinline__ void mma8(float c[4], uint32_t a0, uint32_t a1, uint32_t a2,
                                     uint32_t a3, uint32_t b0, uint32_t b1) {
    asm volatile(
        "mma.sync.aligned.m16n8k8.row.col.f32.tf32.tf32.f32 "
        "{%0,%1,%2,%3}, {%4,%5,%6,%7}, {%8,%9}, {%0,%1,%2,%3};"
        : "+f"(c[0]), "+f"(c[1]), "+f"(c[2]), "+f"(c[3])
        : "r"(a0), "r"(a1), "r"(a2), "r"(a3), "r"(b0), "r"(b1));
}

// ---------------- dense tf32 GEMM: 3-stage cp.async, one sync per k-iter ----------------
#define AST 40
#define ASTG (128 * AST)
#define BSTG (32 * 132)
#define GSTG (ASTG + BSTG)
__global__ __launch_bounds__(256, 2) void mgemm_k(
    const float* __restrict__ A, const float* __restrict__ X,
    float* __restrict__ Cm, const float* __restrict__ bias,
    long long sX, long long sC)
{
    extern __shared__ float gsm[];
    const int tid = threadIdx.x, w = tid >> 5, lane = tid & 31;
    const int g = lane >> 2, tig = lane & 3;
    const int wm = w & 1, wn = w >> 1;

    const float* Ag = A + (long long)blockIdx.y * 128 * 512;
    const float* Xg = X + blockIdx.z * sX + blockIdx.x * 128;
    float* Cg = Cm + blockIdx.z * sC + (long long)blockIdx.y * 128 * 1024 + blockIdx.x * 128;

    const uint32_t sb = (uint32_t)__cvta_generic_to_shared(gsm);

    auto load_stage = [&](int st, int k0) {
        uint32_t abase = sb + (uint32_t)(st * GSTG) * 4u;
        uint32_t bbase = abase + (uint32_t)ASTG * 4u;
#pragma unroll
        for (int p = 0; p < 4; p++) {
            int idx = tid + p * 256;
            int m = idx >> 3, j = idx & 7;
            cp16(abase + (uint32_t)(m * AST + j * 4) * 4u,
                 Ag + (long long)m * 512 + k0 + j * 4);
        }
#pragma unroll
        for (int p = 0; p < 4; p++) {
            int idx = tid + p * 256;
            int k = idx >> 5, j = idx & 31;
            cp16(bbase + (uint32_t)(k * 132 + j * 4) * 4u,
                 Xg + (long long)(k0 + k) * 1024 + j * 4);
        }
        cp_commit();
    };

    float acc[4][4][4];
#pragma unroll
    for (int mt = 0; mt < 4; mt++)
#pragma unroll
        for (int nt = 0; nt < 4; nt++)
#pragma unroll
            for (int i = 0; i < 4; i++) acc[mt][nt][i] = 0.f;

    load_stage(0, 0);
    load_stage(1, 32);

    for (int kb = 0; kb < 16; kb++) {
        const int st = kb % 3;
        if (kb == 15) cp_wait<0>(); else cp_wait<1>();
        __syncthreads();    // stage st visible; also drains reads of stage (kb+2)%3 from iter kb-1
        if (kb < 14) load_stage((kb + 2) % 3, (kb + 2) * 32);

        const float* Asf = gsm + st * GSTG;
        const uint32_t* Bsu = (const uint32_t*)(Asf + ASTG);
#pragma unroll
        for (int ks = 0; ks < 4; ks++) {
            const int kk = ks * 8;
            uint2 a[4][2];
            uint32_t b[4][2];
#pragma unroll
            for (int mt = 0; mt < 4; mt++) {
                int mr = wm * 64 + mt * 16 + g;
                a[mt][0] = *(const uint2*)(Asf + mr * AST + kk + 2 * tig);
                a[mt][1] = *(const uint2*)(Asf + (mr + 8) * AST + kk + 2 * tig);
            }
#pragma unroll
            for (int nt = 0; nt < 4; nt++) {
                int nb = wn * 32 + nt * 8 + g;
                b[nt][0] = Bsu[(kk + 2 * tig) * 132 + nb];
                b[nt][1] = Bsu[(kk + 2 * tig + 1) * 132 + nb];
            }
#pragma unroll
            for (int mt = 0; mt < 4; mt++)
#pragma unroll
                for (int nt = 0; nt < 4; nt++)
                    mma8(acc[mt][nt], a[mt][0].x, a[mt][1].x, a[mt][0].y, a[mt][1].y,
                         b[nt][0], b[nt][1]);
        }
    }

#pragma unroll
    for (int mt = 0; mt < 4; mt++) {
        int mr = wm * 64 + mt * 16 + g;
        float b0v = bias[blockIdx.y * 128 + mr];
        float b1v = bias[blockIdx.y * 128 + mr + 8];
#pragma unroll
        for (int nt = 0; nt < 4; nt++) {
            int nc = wn * 32 + nt * 8 + 2 * tig;
            float2 o0 = make_float2(acc[mt][nt][0] + b0v, acc[mt][nt][1] + b0v);
            float2 o1 = make_float2(acc[mt][nt][2] + b1v, acc[mt][nt][3] + b1v);
            *(float2*)(Cg + (long long)mr * 1024 + nc) = o0;
            *(float2*)(Cg + (long long)(mr + 8) * 1024 + nc) = o1;
        }
    }
}

// ---------------- flash: t-tile 128, P register-resident, 2 CTAs/SM ----------------
// Warp w owns rows [w*16, w*16+16). S C-frags are directly PV A-frags under the
// k-slot remap (c0->a0, c2->a1, c1->a2, c3->a3; ks-block == nt-block).
#define QST 72
#define KST 68
#define VST 72
#define FQOFF 0
#define FKOFF (128 * QST)                 /* 9216 */
#define FKTILE (64 * KST)                 /* 4352 */
#define FVOFF (FKOFF + 2 * FKTILE)        /* 17920 */
#define FVTILE (64 * VST)                 /* 4608 */
#define FSMEM ((FVOFF + 2 * FVTILE) * 4)  /* 108544 B */
#define QSCALE 0.1803368801111204f        /* 0.125 * log2(e) */
__global__ __launch_bounds__(256, 2) void flash_k(
    const float* __restrict__ qkv, float* __restrict__ att)
{
    extern __shared__ float fsm[];
    uint32_t* Qsu = (uint32_t*)fsm;

    const int bh = blockIdx.y;
    const int t0 = blockIdx.x * 128;
    const float* q  = qkv + (long long)bh * 192 * N_;
    const float* kg = q + 64 * N_;
    const float* vg = q + 128 * N_;

    const int tid = threadIdx.x, w = tid >> 5, lane = tid & 31;
    const int g = lane >> 2, tig = lane & 3;
    const int tr = w * 16 + g;

    const uint32_t sb = (uint32_t)__cvta_generic_to_shared(fsm);

    auto load_kv = [&](int st, int s0) {
        int c = tid >> 2, j0 = (tid & 3) * 16;
        uint32_t kd = sb + (uint32_t)(FKOFF + st * FKTILE + c * KST + j0) * 4u;
        uint32_t vd = sb + (uint32_t)(FVOFF + st * FVTILE + c * VST + j0) * 4u;
        const float* ks = kg + (long long)c * N_ + s0 + j0;
        const float* vs = vg + (long long)c * N_ + s0 + j0;
#pragma unroll
        for (int qq = 0; qq < 4; qq++) {
            cp16(kd + qq * 16, ks + qq * 4);
            cp16(vd + qq * 16, vs + qq * 4);
        }
        cp_commit();
    };

    // Q [c][t] -> Qs[t][c], scaled tf32 (one-time)
#pragma unroll
    for (int p = 0; p < 8; p++) {
        int fid = tid + p * 256;
        int c = fid >> 5, t4 = (fid & 31) * 4;
        float4 vq = *(const float4*)(q + (long long)c * N_ + t0 + t4);
        Qsu[(t4 + 0) * QST + c] = f2tf(vq.x * QSCALE);
        Qsu[(t4 + 1) * QST + c] = f2tf(vq.y * QSCALE);
        Qsu[(t4 + 2) * QST + c] = f2tf(vq.z * QSCALE);
        Qsu[(t4 + 3) * QST + c] = f2tf(vq.w * QSCALE);
    }

    load_kv(0, 0);

    float of[8][4];
#pragma unroll
    for (int nt = 0; nt < 8; nt++)
#pragma unroll
        for (int i = 0; i < 4; i++) of[nt][i] = 0.f;
    float m0 = -1e30f, m1 = -1e30f, l0 = 0.f, l1 = 0.f;

    for (int it = 0; it < 16; ++it) {
        const int st = it & 1;
        if (it < 15) load_kv(st ^ 1, (it + 1) * 64);
        if (it < 15) cp_wait<1>(); else cp_wait<0>();
        __syncthreads();    // stage st ready (also covers Q fill at it=0)

        const uint32_t* Ku = (const uint32_t*)(fsm + FKOFF + st * FKTILE);
        const uint32_t* Vu = (const uint32_t*)(fsm + FVOFF + st * FVTILE);

        // S = Q*K : C-frags sf[nt] cover s-cols [nt*8, nt*8+8)
        float sf[8][4];
#pragma unroll
        for (int nt = 0; nt < 8; nt++)
#pragma unroll
            for (int i = 0; i < 4; i++) sf[nt][i] = 0.f;
#pragma unroll
        for (int ks = 0; ks < 8; ks++) {
            const int kk = ks * 8;
            uint2 a0 = *(const uint2*)&Qsu[tr * QST + kk + 2 * tig];
            uint2 a1 = *(const uint2*)&Qsu[(tr + 8) * QST + kk + 2 * tig];
#pragma unroll
            for (int nt = 0; nt < 8; nt++) {
                int nb = nt * 8 + g;
                mma8(sf[nt], a0.x, a1.x, a0.y, a1.y,
                     Ku[(kk + 2 * tig) * KST + nb], Ku[(kk + 2 * tig + 1) * KST + nb]);
            }
        }

        // register online softmax (rows tr, tr+8); probs stay in sf
        float mx0 = -1e30f, mx1 = -1e30f;
#pragma unroll
        for (int nt = 0; nt < 8; nt++) {
            mx0 = fmaxf(mx0, fmaxf(sf[nt][0], sf[nt][1]));
            mx1 = fmaxf(mx1, fmaxf(sf[nt][2], sf[nt][3]));
        }
        mx0 = fmaxf(mx0, __shfl_xor_sync(0xffffffffu, mx0, 1));
        mx0 = fmaxf(mx0, __shfl_xor_sync(0xffffffffu, mx0, 2));
        mx1 = fmaxf(mx1, __shfl_xor_sync(0xffffffffu, mx1, 1));
        mx1 = fmaxf(mx1, __shfl_xor_sync(0xffffffffu, mx1, 2));
        float mn0 = fmaxf(m0, mx0), mn1 = fmaxf(m1, mx1);
        float rs0 = ex2f(m0 - mn0), rs1 = ex2f(m1 - mn1);
        float sum0 = 0.f, sum1 = 0.f;
#pragma unroll
        for (int nt = 0; nt < 8; nt++) {
            sf[nt][0] = ex2f(sf[nt][0] - mn0);
            sf[nt][1] = ex2f(sf[nt][1] - mn0);
            sf[nt][2] = ex2f(sf[nt][2] - mn1);
            sf[nt][3] = ex2f(sf[nt][3] - mn1);
            sum0 += sf[nt][0] + sf[nt][1];
            sum1 += sf[nt][2] + sf[nt][3];
        }
        sum0 += __shfl_xor_sync(0xffffffffu, sum0, 1);
        sum0 += __shfl_xor_sync(0xffffffffu, sum0, 2);
        sum1 += __shfl_xor_sync(0xffffffffu, sum1, 1);
        sum1 += __shfl_xor_sync(0xffffffffu, sum1, 2);
        l0 = l0 * rs0 + sum0;  l1 = l1 * rs1 + sum1;
        m0 = mn0;  m1 = mn1;
#pragma unroll
        for (int nt = 0; nt < 8; nt++) {
            of[nt][0] *= rs0; of[nt][1] *= rs0;
            of[nt][2] *= rs1; of[nt][3] *= rs1;
        }

        // O += P*V : P = sf as A-frags (C-frag layout == A-frag layout under remap);
        // raw float bits as tf32 (P in [0,1], truncation harmless)
#pragma unroll
        for (int ks = 0; ks < 8; ks++) {
            uint32_t a0 = __float_as_uint(sf[ks][0]);
            uint32_t a1 = __float_as_uint(sf[ks][2]);
            uint32_t a2 = __float_as_uint(sf[ks][1]);
            uint32_t a3 = __float_as_uint(sf[ks][3]);
            const int kk = ks * 8;
#pragma unroll
            for (int nt = 0; nt < 8; nt++) {
                uint2 vb = *(const uint2*)&Vu[(nt * 8 + g) * VST + kk + 2 * tig];
                mma8(of[nt], a0, a1, a2, a3, vb.x, vb.y);
            }
        }
        __syncthreads();    // all stage-st reads done before it+1's load overwrites it
    }

    // epilogue: normalize + transpose via smem (Os[64][132] over Q region)
    float li0 = 1.f / l0, li1 = 1.f / l1;
    float* Os = fsm;
#pragma unroll
    for (int nt = 0; nt < 8; nt++) {
        int c = nt * 8 + 2 * tig;
        Os[c * 132 + tr]           = of[nt][0] * li0;
        Os[(c + 1) * 132 + tr]     = of[nt][1] * li0;
        Os[c * 132 + tr + 8]       = of[nt][2] * li1;
        Os[(c + 1) * 132 + tr + 8] = of[nt][3] * li1;
    }
    __syncthreads();
    float* ab = att + (long long)bh * CH * N_;
#pragma unroll
    for (int p = 0; p < 8; p++) {
        int fid = tid + p * 256;
        int c = fid >> 5, t4 = (fid & 31) * 4;
        *(float4*)(ab + (long long)c * N_ + t0 + t4) = *(float4*)&Os[c * 132 + t4];
    }
}

// ---------------- GroupNorm (optionally + residual) ----------------
template<bool RES>
__global__ __launch_bounds__(256) void gn_k(
    const float* __restrict__ in, const float* __restrict__ scale,
    const float* __restrict__ bias, const float* __restrict__ resid,
    float* __restrict__ out)
{
    const int bg = blockIdx.x;
    const int g  = bg % G_;
    const long long base = (long long)bg * CPG * N_;
    const float4* p = (const float4*)(in + base);
    const int tid = threadIdx.x;

    float s = 0.f, ss = 0.f;
    float4 loc[16];
#pragma unroll
    for (int qq = 0; qq < 16; qq++) {
        float4 v = p[tid + qq * 256];
        loc[qq] = v;
        s  += v.x + v.y + v.z + v.w;
        ss += v.x * v.x + v.y * v.y + v.z * v.z + v.w * v.w;
    }
#pragma unroll
    for (int off = 16; off; off >>= 1) {
        s  += __shfl_xor_sync(0xffffffffu, s,  off);
        ss += __shfl_xor_sync(0xffffffffu, ss, off);
    }
    __shared__ float sm[8], sm2[8];
    __shared__ float s_mu, s_r;
    if ((tid & 31) == 0) { sm[tid >> 5] = s; sm2[tid >> 5] = ss; }
    __syncthreads();
    if (tid == 0) {
        float ts = 0.f, tss = 0.f;
#pragma unroll
        for (int i = 0; i < 8; i++) { ts += sm[i]; tss += sm2[i]; }
        float mu  = ts / 16384.f;
        float var = tss / 16384.f - mu * mu;
        s_mu = mu;
        s_r  = rsqrtf(var + EPS);
    }
    __syncthreads();
    const float mu = s_mu, r = s_r;

#pragma unroll
    for (int qq = 0; qq < 16; qq++) {
        int idx = tid + qq * 256;
        int c   = g * CPG + (idx >> 8);
        float sc = scale[c] * r;
        float bi = bias[c] - mu * sc;
        float4 v = loc[qq], o;
        o.x = v.x * sc + bi; o.y = v.y * sc + bi;
        o.z = v.z * sc + bi; o.w = v.w * sc + bi;
        if (RES) {
            float4 rv = ((const float4*)(resid + base))[idx];
            o.x += rv.x; o.y += rv.y; o.z += rv.z; o.w += rv.w;
        }
        ((float4*)(out + base))[idx] = o;
    }
}

// ---------------- launch ----------------
extern "C" void kernel_launch(void* const* d_in, const int* in_sizes, int n_in,
                              void* d_out, int out_size)
{
    const float* x      = (const float*)d_in[0];
    const float* gn1_s  = (const float*)d_in[1];
    const float* gn1_b  = (const float*)d_in[2];
    const float* w_qkv  = (const float*)d_in[3];
    const float* b_qkv  = (const float*)d_in[4];
    const float* w_proj = (const float*)d_in[5];
    const float* b_proj = (const float*)d_in[6];
    const float* gn2_s  = (const float*)d_in[7];
    const float* gn2_b  = (const float*)d_in[8];
    float* out = (float*)d_out;

    float *hn, *qkv, *att, *proj;
    cudaGetSymbolAddress((void**)&hn,   g_hn);
    cudaGetSymbolAddress((void**)&qkv,  g_qkv);
    cudaGetSymbolAddress((void**)&att,  g_att);
    cudaGetSymbolAddress((void**)&proj, g_proj);

    const int gemm_smem = 3 * GSTG * 4;   // 112128 B
    cudaFuncSetAttribute(mgemm_k, cudaFuncAttributeMaxDynamicSharedMemorySize, gemm_smem);
    cudaFuncSetAttribute(flash_k, cudaFuncAttributeMaxDynamicSharedMemorySize, FSMEM);

    // 1) hn = GroupNorm(x)
    gn_k<false><<<B_ * G_, 256>>>(x, gn1_s, gn1_b, nullptr, hn);

    // 2) qkv = w_qkv . hn + b_qkv
    mgemm_k<<<dim3(N_ / 128, 1536 / 128, B_), 256, gemm_smem>>>(
        w_qkv, hn, qkv, b_qkv, (long long)C_ * N_, (long long)3 * C_ * N_);

    // 3) fused attention per (b,h)
    flash_k<<<dim3(N_ / 128, B_ * NH), 256, FSMEM>>>(qkv, att);

    // 4) proj = w_proj . att + b_proj
    mgemm_k<<<dim3(N_ / 128, C_ / 128, B_), 256, gemm_smem>>>(
        w_proj, att, proj, b_proj, (long long)C_ * N_, (long long)C_ * N_);

    // 5) out = x + GroupNorm(proj)
    gn_k<true><<<B_ * G_, 256>>>(proj, gn2_s, gn2_b, x, out);
}

// round 13
// speedup vs baseline: 1.0971x; 1.0971x over previous
#include <cuda_runtime.h>
#include <cstdint>

#define B_  8
#define C_  512
#define N_  1024
#define NH  8
#define CH  64
#define G_  32
#define CPG 16
#define EPS 1e-5f

// ---------------- static scratch ----------------
__device__ float g_hn  [(long long)B_ * C_ * N_];
__device__ float g_qkv [(long long)B_ * 3 * C_ * N_];
__device__ float g_att [(long long)B_ * C_ * N_];
__device__ float g_proj[(long long)B_ * C_ * N_];

// ---------------- helpers ----------------
__device__ __forceinline__ uint32_t f2tf(float f) {
    uint32_t u;
    asm("cvt.rna.tf32.f32 %0, %1;" : "=r"(u) : "f"(f));
    return u;
}
__device__ __forceinline__ float ex2f(float x) {
    float y;
    asm("ex2.approx.f32 %0, %1;" : "=f"(y) : "f"(x));
    return y;
}
__device__ __forceinline__ void cp16(uint32_t dst, const void* src) {
    asm volatile("cp.async.cg.shared.global [%0], [%1], 16;" :: "r"(dst), "l"(src));
}
__device__ __forceinline__ void cp_commit() {
    asm volatile("cp.async.commit_group;" ::: "memory");
}
template<int NN>
__device__ __forceinline__ void cp_wait() {
    asm volatile("cp.async.wait_group %0;" :: "n"(NN) : "memory");
}
// k-slot remap convention: slot tig <-> mem col kk+2*tig, slot tig+4 <-> kk+2*tig+1
// (valid when BOTH A and B follow it; contraction order is irrelevant)
__device__ __forceinline__ void mma8(float c[4], uint32_t a0, uint32_t a1, uint32_t a2,
                                     uint32_t a3, uint32_t b0, uint32_t b1) {
    asm volatile(
        "mma.sync.aligned.m16n8k8.row.col.f32.tf32.tf32.f32 "
        "{%0,%1,%2,%3}, {%4,%5,%6,%7}, {%8,%9}, {%0,%1,%2,%3};"
        : "+f"(c[0]), "+f"(c[1]), "+f"(c[2]), "+f"(c[3])
        : "r"(a0), "r"(a1), "r"(a2), "r"(a3), "r"(b0), "r"(b1));
}

// ---------------- dense tf32 GEMM: 2-stage cp.async (R10 proven version) ----------------
#define AST 40
#define ASTG (128 * AST)
#define BSTG (32 * 132)
__global__ __launch_bounds__(256, 2) void mgemm_k(
    const float* __restrict__ A, const float* __restrict__ X,
    float* __restrict__ Cm, const float* __restrict__ bias,
    long long sX, long long sC)
{
    extern __shared__ float gsm[];
    const int tid = threadIdx.x, w = tid >> 5, lane = tid & 31;
    const int g = lane >> 2, tig = lane & 3;
    const int wm = w & 1, wn = w >> 1;

    const float* Ag = A + (long long)blockIdx.y * 128 * 512;
    const float* Xg = X + blockIdx.z * sX + blockIdx.x * 128;
    float* Cg = Cm + blockIdx.z * sC + (long long)blockIdx.y * 128 * 1024 + blockIdx.x * 128;

    const uint32_t sb = (uint32_t)__cvta_generic_to_shared(gsm);

    auto load_stage = [&](int st, int k0) {
        uint32_t abase = sb + (uint32_t)(st * (ASTG + BSTG)) * 4u;
        uint32_t bbase = abase + (uint32_t)ASTG * 4u;
#pragma unroll
        for (int p = 0; p < 4; p++) {
            int idx = tid + p * 256;
            int m = idx >> 3, j = idx & 7;
            cp16(abase + (uint32_t)(m * AST + j * 4) * 4u,
                 Ag + (long long)m * 512 + k0 + j * 4);
        }
#pragma unroll
        for (int p = 0; p < 4; p++) {
            int idx = tid + p * 256;
            int k = idx >> 5, j = idx & 31;
            cp16(bbase + (uint32_t)(k * 132 + j * 4) * 4u,
                 Xg + (long long)(k0 + k) * 1024 + j * 4);
        }
        cp_commit();
    };

    float acc[4][4][4];
#pragma unroll
    for (int mt = 0; mt < 4; mt++)
#pragma unroll
        for (int nt = 0; nt < 4; nt++)
#pragma unroll
            for (int i = 0; i < 4; i++) acc[mt][nt][i] = 0.f;

    load_stage(0, 0);

    for (int kb = 0; kb < 16; kb++) {
        const int st = kb & 1;
        if (kb < 15) load_stage(st ^ 1, (kb + 1) * 32);
        if (kb < 15) cp_wait<1>(); else cp_wait<0>();
        __syncthreads();

        const float* Asf = gsm + st * (ASTG + BSTG);
        const uint32_t* Bsu = (const uint32_t*)(Asf + ASTG);
#pragma unroll
        for (int ks = 0; ks < 4; ks++) {
            const int kk = ks * 8;
            uint2 a[4][2];
            uint32_t b[4][2];
#pragma unroll
            for (int mt = 0; mt < 4; mt++) {
                int mr = wm * 64 + mt * 16 + g;
                a[mt][0] = *(const uint2*)(Asf + mr * AST + kk + 2 * tig);
                a[mt][1] = *(const uint2*)(Asf + (mr + 8) * AST + kk + 2 * tig);
            }
#pragma unroll
            for (int nt = 0; nt < 4; nt++) {
                int nb = wn * 32 + nt * 8 + g;
                b[nt][0] = Bsu[(kk + 2 * tig) * 132 + nb];
                b[nt][1] = Bsu[(kk + 2 * tig + 1) * 132 + nb];
            }
#pragma unroll
            for (int mt = 0; mt < 4; mt++)
#pragma unroll
                for (int nt = 0; nt < 4; nt++)
                    mma8(acc[mt][nt], a[mt][0].x, a[mt][1].x, a[mt][0].y, a[mt][1].y,
                         b[nt][0], b[nt][1]);
        }
        __syncthreads();
    }

#pragma unroll
    for (int mt = 0; mt < 4; mt++) {
        int mr = wm * 64 + mt * 16 + g;
        float b0v = bias[blockIdx.y * 128 + mr];
        float b1v = bias[blockIdx.y * 128 + mr + 8];
#pragma unroll
        for (int nt = 0; nt < 4; nt++) {
            int nc = wn * 32 + nt * 8 + 2 * tig;
            float2 o0 = make_float2(acc[mt][nt][0] + b0v, acc[mt][nt][1] + b0v);
            float2 o1 = make_float2(acc[mt][nt][2] + b1v, acc[mt][nt][3] + b1v);
            *(float2*)(Cg + (long long)mr * 1024 + nc) = o0;
            *(float2*)(Cg + (long long)(mr + 8) * 1024 + nc) = o1;
        }
    }
}

// ---------------- flash: t-tile 256, 2 m-tiles/warp, register-resident P ----------------
// Warp w owns rows [w*32, w*32+32). S C-frags reused directly as PV A-frags
// (c0->a0, c2->a1, c1->a2, c3->a3; ks-block == nt-block under the k-slot remap).
#define QST 72
#define KST 68
#define VST 72
#define FKOFF (256 * QST)                 /* 18432 */
#define FKTILE (64 * KST)                 /* 4352 */
#define FVOFF (FKOFF + 2 * FKTILE)        /* 27136 */
#define FVTILE (64 * VST)                 /* 4608 */
#define FSMEM ((FVOFF + 2 * FVTILE) * 4)  /* 145408 B */
#define QSCALE 0.1803368801111204f        /* 0.125 * log2(e) */
__global__ __launch_bounds__(256, 1) void flash_k(
    const float* __restrict__ qkv, float* __restrict__ att)
{
    extern __shared__ float fsm[];
    uint32_t* Qsu = (uint32_t*)fsm;

    const int bh = blockIdx.y;
    const int t0 = blockIdx.x * 256;
    const float* q  = qkv + (long long)bh * 192 * N_;
    const float* kg = q + 64 * N_;
    const float* vg = q + 128 * N_;

    const int tid = threadIdx.x, w = tid >> 5, lane = tid & 31;
    const int g = lane >> 2, tig = lane & 3;
    const int r0 = w * 32 + g;

    const uint32_t sb = (uint32_t)__cvta_generic_to_shared(fsm);

    auto load_kv = [&](int st, int s0) {
        int c = tid >> 2, j0 = (tid & 3) * 16;
        uint32_t kd = sb + (uint32_t)(FKOFF + st * FKTILE + c * KST + j0) * 4u;
        uint32_t vd = sb + (uint32_t)(FVOFF + st * FVTILE + c * VST + j0) * 4u;
        const float* ks = kg + (long long)c * N_ + s0 + j0;
        const float* vs = vg + (long long)c * N_ + s0 + j0;
#pragma unroll
        for (int qq = 0; qq < 4; qq++) {
            cp16(kd + qq * 16, ks + qq * 4);
            cp16(vd + qq * 16, vs + qq * 4);
        }
        cp_commit();
    };

    // Q [c][t] -> Qs[t][c], scaled tf32 (one-time)
#pragma unroll
    for (int p = 0; p < 16; p++) {
        int fid = tid + p * 256;
        int c = fid >> 6, t4 = (fid & 63) * 4;
        float4 vq = *(const float4*)(q + (long long)c * N_ + t0 + t4);
        Qsu[(t4 + 0) * QST + c] = f2tf(vq.x * QSCALE);
        Qsu[(t4 + 1) * QST + c] = f2tf(vq.y * QSCALE);
        Qsu[(t4 + 2) * QST + c] = f2tf(vq.z * QSCALE);
        Qsu[(t4 + 3) * QST + c] = f2tf(vq.w * QSCALE);
    }

    load_kv(0, 0);

    float of[2][8][4];
#pragma unroll
    for (int mt = 0; mt < 2; mt++)
#pragma unroll
        for (int nt = 0; nt < 8; nt++)
#pragma unroll
            for (int i = 0; i < 4; i++) of[mt][nt][i] = 0.f;
    float mr_[2][2], lr_[2][2];
#pragma unroll
    for (int mt = 0; mt < 2; mt++) {
        mr_[mt][0] = mr_[mt][1] = -1e30f;
        lr_[mt][0] = lr_[mt][1] = 0.f;
    }

    for (int it = 0; it < 16; ++it) {
        const int st = it & 1;
        if (it < 15) load_kv(st ^ 1, (it + 1) * 64);
        if (it < 15) cp_wait<1>(); else cp_wait<0>();
        __syncthreads();    // stage st ready (also covers Q fill at it=0)

        const uint32_t* Ku = (const uint32_t*)(fsm + FKOFF + st * FKTILE);
        const uint32_t* Vu = (const uint32_t*)(fsm + FVOFF + st * FVTILE);

        // S = Q*K
        float sf[2][8][4];
#pragma unroll
        for (int mt = 0; mt < 2; mt++)
#pragma unroll
            for (int nt = 0; nt < 8; nt++)
#pragma unroll
                for (int i = 0; i < 4; i++) sf[mt][nt][i] = 0.f;
#pragma unroll
        for (int ks = 0; ks < 8; ks++) {
            const int kk = ks * 8;
            uint32_t b[8][2];
#pragma unroll
            for (int nt = 0; nt < 8; nt++) {
                int nb = nt * 8 + g;
                b[nt][0] = Ku[(kk + 2 * tig) * KST + nb];
                b[nt][1] = Ku[(kk + 2 * tig + 1) * KST + nb];
            }
#pragma unroll
            for (int mt = 0; mt < 2; mt++) {
                int rr = r0 + mt * 16;
                uint2 a0 = *(const uint2*)&Qsu[rr * QST + kk + 2 * tig];
                uint2 a1 = *(const uint2*)&Qsu[(rr + 8) * QST + kk + 2 * tig];
#pragma unroll
                for (int nt = 0; nt < 8; nt++)
                    mma8(sf[mt][nt], a0.x, a1.x, a0.y, a1.y, b[nt][0], b[nt][1]);
            }
        }

        // register online softmax per m-tile; probs stay in sf
#pragma unroll
        for (int mt = 0; mt < 2; mt++) {
            float mx0 = -1e30f, mx1 = -1e30f;
#pragma unroll
            for (int nt = 0; nt < 8; nt++) {
                mx0 = fmaxf(mx0, fmaxf(sf[mt][nt][0], sf[mt][nt][1]));
                mx1 = fmaxf(mx1, fmaxf(sf[mt][nt][2], sf[mt][nt][3]));
            }
            mx0 = fmaxf(mx0, __shfl_xor_sync(0xffffffffu, mx0, 1));
            mx0 = fmaxf(mx0, __shfl_xor_sync(0xffffffffu, mx0, 2));
            mx1 = fmaxf(mx1, __shfl_xor_sync(0xffffffffu, mx1, 1));
            mx1 = fmaxf(mx1, __shfl_xor_sync(0xffffffffu, mx1, 2));
            float mn0 = fmaxf(mr_[mt][0], mx0), mn1 = fmaxf(mr_[mt][1], mx1);
            float rs0 = ex2f(mr_[mt][0] - mn0), rs1 = ex2f(mr_[mt][1] - mn1);
            float sum0 = 0.f, sum1 = 0.f;
#pragma unroll
            for (int nt = 0; nt < 8; nt++) {
                sf[mt][nt][0] = ex2f(sf[mt][nt][0] - mn0);
                sf[mt][nt][1] = ex2f(sf[mt][nt][1] - mn0);
                sf[mt][nt][2] = ex2f(sf[mt][nt][2] - mn1);
                sf[mt][nt][3] = ex2f(sf[mt][nt][3] - mn1);
                sum0 += sf[mt][nt][0] + sf[mt][nt][1];
                sum1 += sf[mt][nt][2] + sf[mt][nt][3];
            }
            sum0 += __shfl_xor_sync(0xffffffffu, sum0, 1);
            sum0 += __shfl_xor_sync(0xffffffffu, sum0, 2);
            sum1 += __shfl_xor_sync(0xffffffffu, sum1, 1);
            sum1 += __shfl_xor_sync(0xffffffffu, sum1, 2);
            lr_[mt][0] = lr_[mt][0] * rs0 + sum0;
            lr_[mt][1] = lr_[mt][1] * rs1 + sum1;
            mr_[mt][0] = mn0;  mr_[mt][1] = mn1;
#pragma unroll
            for (int nt = 0; nt < 8; nt++) {
                of[mt][nt][0] *= rs0; of[mt][nt][1] *= rs0;
                of[mt][nt][2] *= rs1; of[mt][nt][3] *= rs1;
            }
        }

        // O += P*V : P = sf as A-frags (raw float bits -> tf32 truncation, P in [0,1])
#pragma unroll
        for (int ks = 0; ks < 8; ks++) {
            const int kk = ks * 8;
            uint2 vb[8];
#pragma unroll
            for (int nt = 0; nt < 8; nt++)
                vb[nt] = *(const uint2*)&Vu[(nt * 8 + g) * VST + kk + 2 * tig];
#pragma unroll
            for (int mt = 0; mt < 2; mt++) {
                uint32_t a0 = __float_as_uint(sf[mt][ks][0]);
                uint32_t a1 = __float_as_uint(sf[mt][ks][2]);
                uint32_t a2 = __float_as_uint(sf[mt][ks][1]);
                uint32_t a3 = __float_as_uint(sf[mt][ks][3]);
#pragma unroll
                for (int nt = 0; nt < 8; nt++)
                    mma8(of[mt][nt], a0, a1, a2, a3, vb[nt].x, vb[nt].y);
            }
        }
        __syncthreads();    // all stage-st reads done before next load overwrites
    }

    // epilogue: normalize + transpose via smem (Os[64][260] over Q region)
    float* Os = fsm;
#pragma unroll
    for (int mt = 0; mt < 2; mt++) {
        int rr = r0 + mt * 16;
        float li0 = 1.f / lr_[mt][0], li1 = 1.f / lr_[mt][1];
#pragma unroll
        for (int nt = 0; nt < 8; nt++) {
            int c = nt * 8 + 2 * tig;
            Os[c * 260 + rr]           = of[mt][nt][0] * li0;
            Os[(c + 1) * 260 + rr]     = of[mt][nt][1] * li0;
            Os[c * 260 + rr + 8]       = of[mt][nt][2] * li1;
            Os[(c + 1) * 260 + rr + 8] = of[mt][nt][3] * li1;
        }
    }
    __syncthreads();
    float* ab = att + (long long)bh * CH * N_;
#pragma unroll
    for (int p = 0; p < 16; p++) {
        int fid = tid + p * 256;
        int c = fid >> 6, t4 = (fid & 63) * 4;
        *(float4*)(ab + (long long)c * N_ + t0 + t4) = *(float4*)&Os[c * 260 + t4];
    }
}

// ---------------- GroupNorm (optionally + residual) ----------------
template<bool RES>
__global__ __launch_bounds__(256) void gn_k(
    const float* __restrict__ in, const float* __restrict__ scale,
    const float* __restrict__ bias, const float* __restrict__ resid,
    float* __restrict__ out)
{
    const int bg = blockIdx.x;
    const int g  = bg % G_;
    const long long base = (long long)bg * CPG * N_;
    const float4* p = (const float4*)(in + base);
    const int tid = threadIdx.x;

    float s = 0.f, ss = 0.f;
    float4 loc[16];
#pragma unroll
    for (int qq = 0; qq < 16; qq++) {
        float4 v = p[tid + qq * 256];
        loc[qq] = v;
        s  += v.x + v.y + v.z + v.w;
        ss += v.x * v.x + v.y * v.y + v.z * v.z + v.w * v.w;
    }
#pragma unroll
    for (int off = 16; off; off >>= 1) {
        s  += __shfl_xor_sync(0xffffffffu, s,  off);
        ss += __shfl_xor_sync(0xffffffffu, ss, off);
    }
    __shared__ float sm[8], sm2[8];
    __shared__ float s_mu, s_r;
    if ((tid & 31) == 0) { sm[tid >> 5] = s; sm2[tid >> 5] = ss; }
    __syncthreads();
    if (tid == 0) {
        float ts = 0.f, tss = 0.f;
#pragma unroll
        for (int i = 0; i < 8; i++) { ts += sm[i]; tss += sm2[i]; }
        float mu  = ts / 16384.f;
        float var = tss / 16384.f - mu * mu;
        s_mu = mu;
        s_r  = rsqrtf(var + EPS);
    }
    __syncthreads();
    const float mu = s_mu, r = s_r;

#pragma unroll
    for (int qq = 0; qq < 16; qq++) {
        int idx = tid + qq * 256;
        int c   = g * CPG + (idx >> 8);
        float sc = scale[c] * r;
        float bi = bias[c] - mu * sc;
        float4 v = loc[qq], o;
        o.x = v.x * sc + bi; o.y = v.y * sc + bi;
        o.z = v.z * sc + bi; o.w = v.w * sc + bi;
        if (RES) {
            float4 rv = ((const float4*)(resid + base))[idx];
            o.x += rv.x; o.y += rv.y; o.z += rv.z; o.w += rv.w;
        }
        ((float4*)(out + base))[idx] = o;
    }
}

// ---------------- launch ----------------
extern "C" void kernel_launch(void* const* d_in, const int* in_sizes, int n_in,
                              void* d_out, int out_size)
{
    const float* x      = (const float*)d_in[0];
    const float* gn1_s  = (const float*)d_in[1];
    const float* gn1_b  = (const float*)d_in[2];
    const float* w_qkv  = (const float*)d_in[3];
    const float* b_qkv  = (const float*)d_in[4];
    const float* w_proj = (const float*)d_in[5];
    const float* b_proj = (const float*)d_in[6];
    const float* gn2_s  = (const float*)d_in[7];
    const float* gn2_b  = (const float*)d_in[8];
    float* out = (float*)d_out;

    float *hn, *qkv, *att, *proj;
    cudaGetSymbolAddress((void**)&hn,   g_hn);
    cudaGetSymbolAddress((void**)&qkv,  g_qkv);
    cudaGetSymbolAddress((void**)&att,  g_att);
    cudaGetSymbolAddress((void**)&proj, g_proj);

    const int gemm_smem = 2 * (ASTG + BSTG) * 4;   // 74752 B
    cudaFuncSetAttribute(mgemm_k, cudaFuncAttributeMaxDynamicSharedMemorySize, gemm_smem);
    cudaFuncSetAttribute(flash_k, cudaFuncAttributeMaxDynamicSharedMemorySize, FSMEM);

    // 1) hn = GroupNorm(x)
    gn_k<false><<<B_ * G_, 256>>>(x, gn1_s, gn1_b, nullptr, hn);

    // 2) qkv = w_qkv . hn + b_qkv
    mgemm_k<<<dim3(N_ / 128, 1536 / 128, B_), 256, gemm_smem>>>(
        w_qkv, hn, qkv, b_qkv, (long long)C_ * N_, (long long)3 * C_ * N_);

    // 3) fused attention per (b,h)
    flash_k<<<dim3(N_ / 256, B_ * NH), 256, FSMEM>>>(qkv, att);

    // 4) proj = w_proj . att + b_proj
    mgemm_k<<<dim3(N_ / 128, C_ / 128, B_), 256, gemm_smem>>>(
        w_proj, att, proj, b_proj, (long long)C_ * N_, (long long)C_ * N_);

    // 5) out = x + GroupNorm(proj)
    gn_k<true><<<B_ * G_, 256>>>(proj, gn2_s, gn2_b, x, out);
}